// round 17
// baseline (speedup 1.0000x reference)
#include <cuda_runtime.h>
#include <cuda.h>
#include <cuda_fp16.h>
#include <math.h>
#include <stdint.h>

#define Bc 4
#define Sc 2048
#define Ec 1024
#define Hc 16
#define Dc 64
#define Mtot (Bc*Sc)   // 8192
#define BH  (Bc*Hc)    // 64

// Scratch (static device globals: allocation-free).
__device__ __half g_Qh[(size_t)BH*Sc*Dc];     // [bh][s][d] fp16
__device__ __half g_Kh[(size_t)BH*Sc*Dc];     // [bh][s][d] fp16
__device__ __half g_Vh[(size_t)BH*Sc*Dc];     // [bh][s][d] fp16 (GEMM output)
__device__ __half g_Vt[(size_t)BH*Dc*Sc];     // [bh][d][s] fp16 (transposed)
__device__ __half g_Ah[(size_t)Bc*Sc*Ec];     // attn output, fp16
__device__ __half g_Xh[(size_t)Mtot*Ec];      // x, fp16
__device__ __half g_Wq[(size_t)Ec*Ec];        // TRANSPOSED [n][k], fp16
__device__ __half g_Wk[(size_t)Ec*Ec];
__device__ __half g_Wv[(size_t)Ec*Ec];
__device__ __half g_Wo[(size_t)Ec*Ec];

// ---- helpers --------------------------------------------------------------
__device__ __forceinline__ uint32_t packh2(float a, float b) {
    __half2 h = __floats2half2_rn(a, b);
    return *(uint32_t*)&h;
}

// fp16 m16n8k16
__device__ __forceinline__ void mma16(float* d, const uint32_t* a, const uint32_t* b) {
    asm volatile(
        "mma.sync.aligned.m16n8k16.row.col.f32.f16.f16.f32 "
        "{%0,%1,%2,%3}, {%4,%5,%6,%7}, {%8,%9}, {%0,%1,%2,%3};"
        : "+f"(d[0]), "+f"(d[1]), "+f"(d[2]), "+f"(d[3])
        : "r"(a[0]), "r"(a[1]), "r"(a[2]), "r"(a[3]), "r"(b[0]), "r"(b[1]));
}

__device__ __forceinline__ void mbar_init(uint32_t a, uint32_t cnt) {
    asm volatile("mbarrier.init.shared.b64 [%0], %1;" :: "r"(a), "r"(cnt) : "memory");
}
__device__ __forceinline__ void mbar_expect(uint32_t a, uint32_t bytes) {
    asm volatile("mbarrier.arrive.expect_tx.shared.b64 _, [%0], %1;"
                 :: "r"(a), "r"(bytes) : "memory");
}
__device__ __forceinline__ void mbar_wait(uint32_t a, uint32_t par) {
    asm volatile(
        "{\n\t.reg .pred P;\n\t"
        "LW%=:\n\t"
        "mbarrier.try_wait.parity.acquire.cta.shared::cta.b64 P, [%0], %1, 0x989680;\n\t"
        "@P bra LD%=;\n\t"
        "bra LW%=;\n\t"
        "LD%=:\n\t}"
        :: "r"(a), "r"(par) : "memory");
}
__device__ __forceinline__ void tma2d(uint32_t dst, const CUtensorMap* m,
                                      int x, int y, uint32_t mb) {
    asm volatile(
        "cp.async.bulk.tensor.2d.shared::cta.global.tile.mbarrier::complete_tx::bytes "
        "[%0], [%1, {%2, %3}], [%4];"
        :: "r"(dst), "l"(m), "r"(x), "r"(y), "r"(mb) : "memory");
}
__device__ __forceinline__ void tma3d(uint32_t dst, const CUtensorMap* m,
                                      int x, int y, int z, uint32_t mb) {
    asm volatile(
        "cp.async.bulk.tensor.3d.shared::cta.global.tile.mbarrier::complete_tx::bytes "
        "[%0], [%1, {%2, %3, %4}], [%5];"
        :: "r"(dst), "l"(m), "r"(x), "r"(y), "r"(z), "r"(mb) : "memory");
}

// ---- pre-convert kernels --------------------------------------------------
__global__ __launch_bounds__(256) void cvt_f16(
    const float* __restrict__ in, __half* __restrict__ out, int n4)
{
    const int i = blockIdx.x * 256 + threadIdx.x;
    if (i < n4) {
        float4 v = ((const float4*)in)[i];
        __half2* o2 = (__half2*)out + 2 * i;
        o2[0] = __floats2half2_rn(v.x, v.y);
        o2[1] = __floats2half2_rn(v.z, v.w);
    }
}

// transpose + convert all 4 weights in one launch (z selects matrix)
__global__ __launch_bounds__(256) void cvt_tr16_all(
    const float* __restrict__ i0, const float* __restrict__ i1,
    const float* __restrict__ i2, const float* __restrict__ i3,
    __half* __restrict__ o0, __half* __restrict__ o1,
    __half* __restrict__ o2, __half* __restrict__ o3)
{
    __shared__ float t[32][33];
    const int z = blockIdx.z;
    const float* in = (z == 0) ? i0 : (z == 1) ? i1 : (z == 2) ? i2 : i3;
    __half* out     = (z == 0) ? o0 : (z == 1) ? o1 : (z == 2) ? o2 : o3;
    const int n0 = blockIdx.x * 32, k0 = blockIdx.y * 32;
    const int tx = threadIdx.x & 31, ty = threadIdx.x >> 5;
    #pragma unroll
    for (int j = 0; j < 4; j++)
        t[ty * 4 + j][tx] = in[(size_t)(k0 + ty * 4 + j) * Ec + n0 + tx];
    __syncthreads();
    #pragma unroll
    for (int j = 0; j < 4; j++)
        out[(size_t)(n0 + ty * 4 + j) * Ec + k0 + tx] =
            __float2half_rn(t[tx][ty * 4 + j]);
}

// per-head fp16 transpose: g_Vh [bh][s][d] -> g_Vt [bh][d][s]
__global__ __launch_bounds__(256) void tr_v(
    const __half* __restrict__ in, __half* __restrict__ out)
{
    __shared__ __half t[32][34];
    const int s0 = blockIdx.x * 32, d0 = blockIdx.y * 32, bh = blockIdx.z;
    const int tx = threadIdx.x & 31, ty = threadIdx.x >> 5;
    const size_t bi = (size_t)bh * Sc * Dc;
    const size_t bo = (size_t)bh * Dc * Sc;
    #pragma unroll
    for (int j = 0; j < 4; j++)
        t[ty * 4 + j][tx] = in[bi + (size_t)(s0 + ty * 4 + j) * Dc + d0 + tx];
    __syncthreads();
    #pragma unroll
    for (int j = 0; j < 4; j++)
        out[bo + (size_t)(d0 + ty * 4 + j) * Sc + s0 + tx] = t[tx][ty * 4 + j];
}

// ---------------- GEMM fp16 (TMA, 3-stage, fused z) ------------------------
// A smem [128 m][64 k] halves SW128 (32 words/row), W smem [128 n][64 k].
// 128x128 tile, BK=64, 256 threads, warp tile 64x32, m16n8k16.
// MODE 1: QKV projection -- all z write fp16 [bh][s][d] coalesced.
// MODE 0: final, f32 row-major.
#define GBM 128
#define GBN 128
#define GBK 64
#define GSTG 32768
#define GMB  98304
#define GSMEM 98328

template<int MODE>
__global__ __launch_bounds__(256, 2) void gemm_tc(
    const __grid_constant__ CUtensorMap mA,
    const __grid_constant__ CUtensorMap mW0,
    const __grid_constant__ CUtensorMap mW1,
    const __grid_constant__ CUtensorMap mW2,
    const float* __restrict__ b0, const float* __restrict__ b1,
    const float* __restrict__ b2,
    void* __restrict__ C0, void* __restrict__ C1, void* __restrict__ C2)
{
    extern __shared__ char smem[];
    uint32_t smb;
    asm("{ .reg .u64 t; cvta.to.shared.u64 t, %1; cvt.u32.u64 %0, t; }"
        : "=r"(smb) : "l"(smem));

    const int z = blockIdx.z;
    const CUtensorMap* mW = (z == 0) ? &mW0 : (z == 1) ? &mW1 : &mW2;
    const float* bias = (z == 0) ? b0 : (z == 1) ? b1 : b2;
    void* C = (z == 0) ? C0 : (z == 1) ? C1 : C2;

    const int tid  = threadIdx.x;
    const int lane = tid & 31, warp = tid >> 5;
    const int g = lane >> 2, tg = lane & 3;
    const int wm = warp >> 2, wn = warp & 3;
    const int bm = blockIdx.y * GBM, bn = blockIdx.x * GBN;
    const int xg = 4 * g;

    if (tid == 0) {
        mbar_init(smb + GMB, 1); mbar_init(smb + GMB + 8, 1);
        mbar_init(smb + GMB + 16, 1);
    }
    __syncthreads();
    if (tid == 0) {
        #pragma unroll
        for (int s = 0; s < 2; s++) {
            const uint32_t mb = smb + GMB + 8 * s;
            mbar_expect(mb, GSTG);
            tma2d(smb + GSTG * s,         &mA, s * GBK, bm, mb);
            tma2d(smb + GSTG * s + 16384, mW,  s * GBK, bn, mb);
        }
    }

    float acc[4][4][4];
    #pragma unroll
    for (int mt = 0; mt < 4; mt++)
        #pragma unroll
        for (int nt = 0; nt < 4; nt++)
            #pragma unroll
            for (int i = 0; i < 4; i++) acc[mt][nt][i] = 0.f;

    const int NIT = Ec / GBK;   // 16
    for (int it = 0; it < NIT; it++) {
        const int sl = it % 3;
        if (it) __syncthreads();
        if (tid == 0 && it + 2 < NIT) {
            const int s2 = (it + 2) % 3;
            const uint32_t mb = smb + GMB + 8 * s2;
            mbar_expect(mb, GSTG);
            tma2d(smb + GSTG * s2,         &mA, (it + 2) * GBK, bm, mb);
            tma2d(smb + GSTG * s2 + 16384, mW,  (it + 2) * GBK, bn, mb);
        }
        mbar_wait(smb + GMB + 8 * sl, (it / 3) & 1);

        const uint32_t* Au = (const uint32_t*)(smem + GSTG * sl);
        const uint32_t* Wu = (const uint32_t*)(smem + GSTG * sl + 16384);

        #pragma unroll
        for (int ks = 0; ks < 4; ks++) {
            const int c0 = (8 * ks + tg) ^ xg;
            const int c4 = (8 * ks + tg + 4) ^ xg;
            uint32_t af[4][4], bf[4][2];
            #pragma unroll
            for (int mt = 0; mt < 4; mt++) {
                const int r = wm * 64 + mt * 16 + g;
                af[mt][0] = Au[r * 32 + c0];
                af[mt][1] = Au[(r + 8) * 32 + c0];
                af[mt][2] = Au[r * 32 + c4];
                af[mt][3] = Au[(r + 8) * 32 + c4];
            }
            #pragma unroll
            for (int nt = 0; nt < 4; nt++) {
                const int cb = wn * 32 + nt * 8 + g;
                bf[nt][0] = Wu[cb * 32 + c0];
                bf[nt][1] = Wu[cb * 32 + c4];
            }
            #pragma unroll
            for (int mt = 0; mt < 4; mt++)
                #pragma unroll
                for (int nt = 0; nt < 4; nt++)
                    mma16(acc[mt][nt], af[mt], bf[nt]);
        }
    }

    #pragma unroll
    for (int mt = 0; mt < 4; mt++) {
        #pragma unroll
        for (int half = 0; half < 2; half++) {
            const int m = bm + wm * 64 + mt * 16 + g + half * 8;
            #pragma unroll
            for (int nt = 0; nt < 4; nt++) {
                const int n = bn + wn * 32 + nt * 8 + 2 * tg;
                float2 bb = *(const float2*)&bias[n];
                float v0 = acc[mt][nt][half * 2 + 0] + bb.x;
                float v1 = acc[mt][nt][half * 2 + 1] + bb.y;
                if (MODE == 1) {
                    const int b = m >> 11, s = m & 2047;
                    const int h = n >> 6, d = n & 63;
                    __half* Ch = (__half*)C;
                    *(__half2*)&Ch[(((size_t)(b * Hc + h)) * Sc + s) * Dc + d] =
                        __floats2half2_rn(v0, v1);
                } else {
                    *(float2*)&((float*)C)[(size_t)m * Ec + n] =
                        make_float2(v0, v1);
                }
            }
        }
    }
}

// ---------------- Flash attention (fp16 mma, P in regs, all-TMA) -----------
// Unchanged from R15 (proven).
#define AQ 128
#define AK0 16384
#define AMB 49152
#define ASMEM 49176

__global__ __launch_bounds__(256, 2) void attn_tc(
    __half* __restrict__ Ag_,
    const __grid_constant__ CUtensorMap mQ,
    const __grid_constant__ CUtensorMap mK,
    const __grid_constant__ CUtensorMap mV)
{
    extern __shared__ char smem[];
    uint32_t smb;
    asm("{ .reg .u64 t; cvta.to.shared.u64 t, %1; cvt.u32.u64 %0, t; }"
        : "=r"(smb) : "l"(smem));

    const int tid  = threadIdx.x;
    const int lane = tid & 31, warp = tid >> 5;
    const int g = lane >> 2, tg = lane & 3;
    const int q0 = warp * 16;
    const int xg = 4 * g;

    const int qt = blockIdx.x, h = blockIdx.y, b = blockIdx.z;
    const int bh = b * Hc + h;

    if (tid == 0) {
        mbar_init(smb + AMB, 1); mbar_init(smb + AMB + 8, 1);
        mbar_init(smb + AMB + 16, 1);
    }
    __syncthreads();
    if (tid == 0) {
        mbar_expect(smb + AMB + 16, 16384);
        tma3d(smb, &mQ, 0, qt * AQ, bh, smb + AMB + 16);
        mbar_expect(smb + AMB, 16384);
        tma3d(smb + AK0,        &mK, 0, 0, bh, smb + AMB);
        tma3d(smb + AK0 + 8192, &mV, 0, 0, bh, smb + AMB);
    }

    float o[8][4];
    float mrow[2], lrow[2];
    #pragma unroll
    for (int nt = 0; nt < 8; nt++)
        #pragma unroll
        for (int i = 0; i < 4; i++) o[nt][i] = 0.f;
    mrow[0] = mrow[1] = -INFINITY;
    lrow[0] = lrow[1] = 0.f;

    mbar_wait(smb + AMB + 16, 0);
    const uint32_t* Qu = (const uint32_t*)smem;

    const int NT = Sc / 64;
    for (int kt = 0; kt < NT; kt++) {
        const int p = kt & 1;
        if (kt) __syncthreads();
        if (tid == 0 && kt + 1 < NT) {
            const uint32_t mb = smb + AMB + 8 * (1 - p);
            const int kv0 = (kt + 1) * 64;
            mbar_expect(mb, 16384);
            tma3d(smb + AK0 + 16384 * (1 - p),        &mK, 0, kv0, bh, mb);
            tma3d(smb + AK0 + 16384 * (1 - p) + 8192, &mV, kv0, 0, bh, mb);
        }
        mbar_wait(smb + AMB + 8 * p, (kt >> 1) & 1);

        const uint32_t* Ku = (const uint32_t*)(smem + AK0 + 16384 * p);
        const uint32_t* Vu = (const uint32_t*)(smem + AK0 + 16384 * p + 8192);

        float s[8][4];
        #pragma unroll
        for (int nt = 0; nt < 8; nt++)
            #pragma unroll
            for (int i = 0; i < 4; i++) s[nt][i] = 0.f;

        #pragma unroll
        for (int ks = 0; ks < 4; ks++) {
            const int c0 = (8 * ks + tg) ^ xg;
            const int c4 = (8 * ks + tg + 4) ^ xg;
            uint32_t af[4];
            af[0] = Qu[(q0 + g) * 32 + c0];
            af[1] = Qu[(q0 + 8 + g) * 32 + c0];
            af[2] = Qu[(q0 + g) * 32 + c4];
            af[3] = Qu[(q0 + 8 + g) * 32 + c4];
            #pragma unroll
            for (int nt = 0; nt < 8; nt++) {
                const int row = (8 * nt + g) * 32;
                uint32_t bf[2];
                bf[0] = Ku[row + c0];
                bf[1] = Ku[row + c4];
                mma16(s[nt], af, bf);
            }
        }

        #pragma unroll
        for (int half = 0; half < 2; half++) {
            float tmax = -INFINITY;
            #pragma unroll
            for (int nt = 0; nt < 8; nt++) {
                s[nt][half * 2 + 0] *= 0.125f;
                s[nt][half * 2 + 1] *= 0.125f;
                tmax = fmaxf(tmax, s[nt][half * 2 + 0]);
                tmax = fmaxf(tmax, s[nt][half * 2 + 1]);
            }
            tmax = fmaxf(tmax, __shfl_xor_sync(0xffffffffu, tmax, 1));
            tmax = fmaxf(tmax, __shfl_xor_sync(0xffffffffu, tmax, 2));
            const float mn   = fmaxf(mrow[half], tmax);
            const float corr = __expf(mrow[half] - mn);
            float rs = 0.f;
            #pragma unroll
            for (int nt = 0; nt < 8; nt++) {
                float p0 = __expf(s[nt][half * 2 + 0] - mn);
                float p1 = __expf(s[nt][half * 2 + 1] - mn);
                s[nt][half * 2 + 0] = p0;
                s[nt][half * 2 + 1] = p1;
                rs += p0 + p1;
                o[nt][half * 2 + 0] *= corr;
                o[nt][half * 2 + 1] *= corr;
            }
            rs += __shfl_xor_sync(0xffffffffu, rs, 1);
            rs += __shfl_xor_sync(0xffffffffu, rs, 2);
            lrow[half] = lrow[half] * corr + rs;
            mrow[half] = mn;
        }

        #pragma unroll
        for (int ks = 0; ks < 4; ks++) {
            uint32_t af[4];
            af[0] = packh2(s[2 * ks][0],     s[2 * ks][1]);
            af[1] = packh2(s[2 * ks][2],     s[2 * ks][3]);
            af[2] = packh2(s[2 * ks + 1][0], s[2 * ks + 1][1]);
            af[3] = packh2(s[2 * ks + 1][2], s[2 * ks + 1][3]);
            const int c0 = (8 * ks + tg) ^ xg;
            const int c4 = (8 * ks + tg + 4) ^ xg;
            #pragma unroll
            for (int nt = 0; nt < 8; nt++) {
                const int row = (8 * nt + g) * 32;
                uint32_t bf[2];
                bf[0] = Vu[row + c0];
                bf[1] = Vu[row + c4];
                mma16(o[nt], af, bf);
            }
        }
    }

    #pragma unroll
    for (int half = 0; half < 2; half++) {
        const float inv = 1.f / lrow[half];
        const int q = qt * AQ + q0 + g + half * 8;
        #pragma unroll
        for (int nt = 0; nt < 8; nt++) {
            const int d = nt * 8 + 2 * tg;
            __half2* dst = (__half2*)&Ag_[((size_t)b * Sc + q) * Ec + h * Dc + d];
            *dst = __floats2half2_rn(o[nt][half * 2 + 0] * inv,
                                     o[nt][half * 2 + 1] * inv);
        }
    }
}

// ---------------------------------------------------------------------------
typedef CUresult (*PFN_tmencode)(
    CUtensorMap*, CUtensorMapDataType, cuuint32_t, void*,
    const cuuint64_t*, const cuuint64_t*, const cuuint32_t*, const cuuint32_t*,
    CUtensorMapInterleave, CUtensorMapSwizzle, CUtensorMapL2promotion,
    CUtensorMapFloatOOBfill);

static void enc2d(PFN_tmencode fn, CUtensorMap* m, void* base,
                  uint64_t d0, uint64_t d1, uint64_t stride1B,
                  uint32_t b0, uint32_t b1)
{
    cuuint64_t dims[2] = {d0, d1};
    cuuint64_t str[1]  = {stride1B};
    cuuint32_t box[2]  = {b0, b1};
    cuuint32_t es[2]   = {1, 1};
    fn(m, CU_TENSOR_MAP_DATA_TYPE_FLOAT16, 2, base, dims, str, box, es,
       CU_TENSOR_MAP_INTERLEAVE_NONE, CU_TENSOR_MAP_SWIZZLE_128B,
       CU_TENSOR_MAP_L2_PROMOTION_L2_128B, CU_TENSOR_MAP_FLOAT_OOB_FILL_NONE);
}

static void enc3d(PFN_tmencode fn, CUtensorMap* m, void* base,
                  uint64_t d0, uint64_t d1, uint32_t b0, uint32_t b1)
{
    cuuint64_t dims[3] = {d0, d1, BH};
    cuuint64_t str[2]  = {d0 * 2ull, d0 * d1 * 2ull};
    cuuint32_t box[3]  = {b0, b1, 1};
    cuuint32_t es[3]   = {1, 1, 1};
    fn(m, CU_TENSOR_MAP_DATA_TYPE_FLOAT16, 3, base, dims, str, box, es,
       CU_TENSOR_MAP_INTERLEAVE_NONE, CU_TENSOR_MAP_SWIZZLE_128B,
       CU_TENSOR_MAP_L2_PROMOTION_L2_128B, CU_TENSOR_MAP_FLOAT_OOB_FILL_NONE);
}

extern "C" void kernel_launch(void* const* d_in, const int* in_sizes, int n_in,
                              void* d_out, int out_size)
{
    const float* x  = (const float*)d_in[0];
    const float* Wq = (const float*)d_in[1];
    const float* bq = (const float*)d_in[2];
    const float* Wk = (const float*)d_in[3];
    const float* bk = (const float*)d_in[4];
    const float* Wv = (const float*)d_in[5];
    const float* bv = (const float*)d_in[6];
    const float* Wo = (const float*)d_in[7];
    const float* bo = (const float*)d_in[8];
    float* out = (float*)d_out;

    __half *pQ, *pK, *pVh, *pVt, *pAh, *pXh, *pWq, *pWk, *pWv, *pWo;
    cudaGetSymbolAddress((void**)&pQ,  g_Qh);
    cudaGetSymbolAddress((void**)&pK,  g_Kh);
    cudaGetSymbolAddress((void**)&pVh, g_Vh);
    cudaGetSymbolAddress((void**)&pVt, g_Vt);
    cudaGetSymbolAddress((void**)&pAh, g_Ah);
    cudaGetSymbolAddress((void**)&pXh, g_Xh);
    cudaGetSymbolAddress((void**)&pWq, g_Wq);
    cudaGetSymbolAddress((void**)&pWk, g_Wk);
    cudaGetSymbolAddress((void**)&pWv, g_Wv);
    cudaGetSymbolAddress((void**)&pWo, g_Wo);

    PFN_tmencode enc = nullptr;
    {
        void* fn = nullptr;
        cudaDriverEntryPointQueryResult qr;
        cudaGetDriverEntryPointByVersion("cuTensorMapEncodeTiled", &fn, 12000,
                                         cudaEnableDefault, &qr);
        enc = (PFN_tmencode)fn;
    }

    CUtensorMap mX, mWq, mWk, mWv, mWo, mAo, mQm, mKm, mVm;
    enc2d(enc, &mX,  pXh, Ec, Mtot, Ec * 2ull, GBK, GBM);
    enc2d(enc, &mWq, pWq, Ec, Ec,   Ec * 2ull, GBK, GBN);
    enc2d(enc, &mWk, pWk, Ec, Ec,   Ec * 2ull, GBK, GBN);
    enc2d(enc, &mWv, pWv, Ec, Ec,   Ec * 2ull, GBK, GBN);
    enc2d(enc, &mWo, pWo, Ec, Ec,   Ec * 2ull, GBK, GBN);
    enc2d(enc, &mAo, pAh, Ec, Mtot, Ec * 2ull, GBK, GBM);
    enc3d(enc, &mQm, pQ,  Dc, Sc, 64, 128);   // [bh][s][d], box 64d x 128q
    enc3d(enc, &mKm, pK,  Dc, Sc, 64, 64);    // [bh][s][d], box 64d x 64kv
    enc3d(enc, &mVm, pVt, Sc, Dc, 64, 64);    // [bh][d][s], box 64s x 64d

    cudaFuncSetAttribute(gemm_tc<0>, cudaFuncAttributeMaxDynamicSharedMemorySize, GSMEM);
    cudaFuncSetAttribute(gemm_tc<1>, cudaFuncAttributeMaxDynamicSharedMemorySize, GSMEM);
    cudaFuncSetAttribute(attn_tc, cudaFuncAttributeMaxDynamicSharedMemorySize, ASMEM);

    const int xN4 = Mtot * Ec / 4;
    cvt_f16<<<(xN4 + 255) / 256, 256>>>(x, pXh, xN4);
    cvt_tr16_all<<<dim3(Ec / 32, Ec / 32, 4), 256>>>(
        Wq, Wk, Wv, Wo, pWq, pWk, pWv, pWo);

    // fused Q/K/V projection (fp16): all z write coalesced [bh][s][d]
    gemm_tc<1><<<dim3(Ec / GBN, Mtot / GBM, 3), 256, GSMEM>>>(
        mX, mWq, mWk, mWv, bq, bk, bv, pQ, pK, pVh);
    // transpose V per head: [bh][s][d] -> [bh][d][s]
    tr_v<<<dim3(Sc / 32, Dc / 32, BH), 256>>>(pVh, pVt);
    attn_tc<<<dim3(Sc / AQ, Hc, Bc), 256, ASMEM>>>(pAh, mQm, mKm, mVm);
    gemm_tc<0><<<dim3(Ec / GBN, Mtot / GBM, 1), 256, GSMEM>>>(
        mAo, mWo, mWo, mWo, bo, bo, bo, out, out, out);
}